// round 16
// baseline (speedup 1.0000x reference)
#include <cuda_runtime.h>
#include <cuda_bf16.h>
#include <cstdint>

struct P12 { const float* W[4]; const float* B[4]; const float* R[4]; };

// ---------------- persistent device scratch (no allocations allowed) --------
__device__ float g_X[(size_t)512 * 256 * 1024];   // pre-activations [t][b][g*256+u]
__device__ __nv_bfloat16 g_hH[2][256 * 256];      // h hi, ping-pong
__device__ __nv_bfloat16 g_hL[2][256 * 256];      // h lo
__device__ unsigned g_flags[128 * 32];            // per-CTA barrier flags (128B apart)
__device__ __nv_bfloat16 g_Ahi[(size_t)131072 * 512];
__device__ __nv_bfloat16 g_Alo[(size_t)131072 * 512];
__device__ __nv_bfloat16 g_Whi[1024 * 512];       // W (input cols) hi
__device__ __nv_bfloat16 g_Wlo[1024 * 512];

// ---------------- helpers ----------------------------------------------------
__device__ __forceinline__ float ex2a(float x) {
    float r; asm("ex2.approx.f32 %0, %1;" : "=f"(r) : "f"(x)); return r;
}
__device__ __forceinline__ float rcpa(float x) {
    float r; asm("rcp.approx.f32 %0, %1;" : "=f"(r) : "f"(x)); return r;
}
__device__ __forceinline__ float sigm_fast(float x) {
    return rcpa(1.0f + ex2a(-1.4426950408889634f * x));
}
__device__ __forceinline__ float tanh_fast(float x) {
    return 1.0f - 2.0f * rcpa(1.0f + ex2a(2.8853900817779268f * x));
}
__device__ __forceinline__ uint32_t smem_u32(const void* p) {
    uint32_t a; asm("{ .reg .u64 t; cvta.to.shared.u64 t, %1; cvt.u32.u64 %0, t; }"
                    : "=r"(a) : "l"(p)); return a;
}
__device__ __forceinline__ void st_release(unsigned* p, unsigned v) {
    asm volatile("st.release.gpu.u32 [%0], %1;" :: "l"(p), "r"(v) : "memory");
}
__device__ __forceinline__ unsigned ld_acquire(const unsigned* p) {
    unsigned v; asm volatile("ld.acquire.gpu.u32 %0, [%1];" : "=r"(v) : "l"(p) : "memory");
    return v;
}
__device__ __forceinline__ void cpa16(uint32_t smem, const void* g) {
    asm volatile("cp.async.cg.shared.global [%0], [%1], 16;" :: "r"(smem), "l"(g));
}
#define CP_COMMIT() asm volatile("cp.async.commit_group;" ::: "memory")
#define CP_WAIT(n)  asm volatile("cp.async.wait_group %0;" :: "n"(n) : "memory")
#define SWZ(x) ((x) ^ (((x) >> 3) & 0x70))

__device__ __forceinline__ void ldsm_x4(uint32_t& r0, uint32_t& r1, uint32_t& r2,
                                        uint32_t& r3, uint32_t addr) {
    asm volatile("ldmatrix.sync.aligned.m8n8.x4.shared.b16 {%0,%1,%2,%3}, [%4];"
                 : "=r"(r0), "=r"(r1), "=r"(r2), "=r"(r3) : "r"(addr));
}
__device__ __forceinline__ void mma16816(float* d, const uint32_t* a,
                                         uint32_t b0, uint32_t b1) {
    asm volatile("mma.sync.aligned.m16n8k16.row.col.f32.bf16.bf16.f32 "
                 "{%0,%1,%2,%3}, {%4,%5,%6,%7}, {%8,%9}, {%0,%1,%2,%3};"
                 : "+f"(d[0]), "+f"(d[1]), "+f"(d[2]), "+f"(d[3])
                 : "r"(a[0]), "r"(a[1]), "r"(a[2]), "r"(a[3]), "r"(b0), "r"(b1));
}

// ---------------------------------------------------------------------------
// Merged conversion: blocks 0..2047 convert W, blocks 2048..6143 convert x.
// ---------------------------------------------------------------------------
__global__ void cvt_kernel(const float* __restrict__ A, P12 p) {
    int bid = blockIdx.x, tid = threadIdx.x;
    if (bid < 2048) {
        int i = bid * 256 + tid;
        if (i >= 1024 * 512) return;
        int nrow = i >> 9, k = i & 511;
        int g = nrow >> 8, u = nrow & 255;
        float v = p.W[g][(size_t)u * 768 + k];
        __nv_bfloat16 h = __float2bfloat16(v);
        g_Whi[i] = h;
        g_Wlo[i] = __float2bfloat16(v - __bfloat162float(h));
    } else {
        size_t i = (size_t)(bid - 2048) * 256 + tid;
        size_t n = (size_t)131072 * 512;
        for (; i < n; i += (size_t)4096 * 256) {
            float v = A[i];
            __nv_bfloat16 h = __float2bfloat16(v);
            g_Ahi[i] = h;
            g_Alo[i] = __float2bfloat16(v - __bfloat162float(h));
        }
    }
}

// ---------------------------------------------------------------------------
// Kernel 1: X[m][n] = x[m].W[n] + (b+r)[n]
//   CTA 128m x 128n, grid (8,1024). 3-stage cp.async (32KB/stage, 96KB),
//   2 CTAs/SM, 64x32 warp tiles. 24 chunks, CHUNK-MAJOR pass order:
//   sp = c%3 (hi.hi, lo.hi, hi.lo), kc = c/3 — A-hi re-read 2 chunks apart
//   (L2-hot) instead of 16.
// ---------------------------------------------------------------------------
__global__ void __launch_bounds__(256, 2) g1mma_kernel(P12 p) {
    extern __shared__ __align__(1024) char sh[];
    uint32_t sb = smem_u32(sh);
    const int tid = threadIdx.x, wid = tid >> 5, lane = tid & 31;
    const int bx = blockIdx.x, n0 = bx * 128;
    const int gate = bx >> 1, ub = (bx & 1) * 128;
    const int m0 = blockIdx.y * 128;
    const int mw = (wid >> 2) * 64, nw = (wid & 3) * 32;

    const __nv_bfloat16* Asrc[3] = { g_Ahi, g_Alo, g_Ahi };
    const __nv_bfloat16* Bsrc[3] = { g_Whi, g_Whi, g_Wlo };

    float d[4][4][4];
#pragma unroll
    for (int i = 0; i < 4; i++)
#pragma unroll
        for (int j = 0; j < 4; j++)
#pragma unroll
            for (int q = 0; q < 4; q++) d[i][j][q] = 0.f;

    const int frow = tid >> 1, fsl = (tid & 1) * 4;  // 2 threads/row, 4 slots each

    auto stage_fill = [&](int c, int s) {
        int sp = c % 3, kc = (c / 3) << 6;           // chunk-major pass order
        const __nv_bfloat16* Ap = Asrc[sp] + (size_t)(m0 + frow) * 512 + kc;
        const __nv_bfloat16* Bp = Bsrc[sp] + (size_t)(n0 + frow) * 512 + kc;
        uint32_t ab = sb + s * 32768;
        uint32_t bb = ab + 16384;
#pragma unroll
        for (int j = 0; j < 4; j++) {
            cpa16(ab + SWZ((uint32_t)(frow * 128 + (fsl + j) * 16)), Ap + (fsl + j) * 8);
            cpa16(bb + SWZ((uint32_t)(frow * 128 + (fsl + j) * 16)), Bp + (fsl + j) * 8);
        }
    };

    stage_fill(0, 0); CP_COMMIT();
    stage_fill(1, 1); CP_COMMIT();

    int cs = 0, fs = 2;                      // compute stage, fill stage
    for (int c = 0; c < 24; c++) {
        CP_WAIT(1);                           // group c drained
        __syncthreads();
        if (c + 2 < 24) { stage_fill(c + 2, fs); }
        CP_COMMIT();

        const uint32_t sA = sb + cs * 32768, sB = sA + 16384;
#pragma unroll
        for (int k16 = 0; k16 < 4; k16++) {
            const uint32_t colb = k16 * 32 + ((lane >> 4) << 4);
            uint32_t a[4][4], b[2][4];
#pragma unroll
            for (int im = 0; im < 4; im++) {
                int r = mw + im * 16 + (lane & 15);
                ldsm_x4(a[im][0], a[im][1], a[im][2], a[im][3],
                        sA + SWZ((uint32_t)(r * 128 + colb)));
            }
#pragma unroll
            for (int jn = 0; jn < 2; jn++) {
                int r = nw + jn * 16 + (lane & 15);
                ldsm_x4(b[jn][0], b[jn][1], b[jn][2], b[jn][3],
                        sB + SWZ((uint32_t)(r * 128 + colb)));
            }
#pragma unroll
            for (int im = 0; im < 4; im++)
#pragma unroll
                for (int j = 0; j < 4; j++)
                    mma16816(d[im][j], a[im], b[j >> 1][j & 1], b[j >> 1][2 + (j & 1)]);
        }
        cs = (cs == 2) ? 0 : cs + 1;
        fs = (fs == 2) ? 0 : fs + 1;
    }

    // epilogue: registers -> g_X with bias+rot
#pragma unroll
    for (int j = 0; j < 4; j++) {
        int nl = nw + j * 8 + (lane & 3) * 2;
        int u = ub + nl;
        float bv0 = p.B[gate][u] + p.R[gate][u];
        float bv1 = p.B[gate][u + 1] + p.R[gate][u + 1];
#pragma unroll
        for (int im = 0; im < 4; im++) {
            int m = m0 + mw + im * 16 + (lane >> 2);
            float2 v0 = { d[im][j][0] + bv0, d[im][j][1] + bv1 };
            float2 v1 = { d[im][j][2] + bv0, d[im][j][3] + bv1 };
            *(float2*)(g_X + (size_t)m * 1024 + n0 + nl) = v0;
            *(float2*)(g_X + (size_t)(m + 8) * 1024 + n0 + nl) = v1;
        }
    }
}

// ---------------------------------------------------------------------------
// Kernel 2: persistent recurrence, tensorized — R11/R15 structure; h-fill
// now via cp.async.cg (L1-bypass preserved, one less reg/LSU hop per step).
// Grid (8 unit-tiles, 16 batch-groups), 512 threads = 16 warps.
// ---------------------------------------------------------------------------
__global__ void __launch_bounds__(512, 1) rnn_mma_kernel(P12 p, float* __restrict__ out,
                                                         int out_elems) {
    extern __shared__ __align__(16) char shm[];
    float* PS = (float*)(shm + 16896);
    const uint32_t sb = smem_u32(shm);

    const int tid = threadIdx.x, w = tid >> 5, lane = tid & 31;
    const int kg = w & 3, nt = w >> 2;               // kg 0..3, nt 0..3
    const int b = tid >> 5, u = tid & 31;            // gate-phase: batch=warp, unit=lane
    const int u0 = blockIdx.x * 32, by = blockIdx.y, b0 = by * 16;
    const int myflag = by * 8 + blockIdx.x;

    // ---- init: stage Wh (hidden cols) as bf16, ldsm frags to registers
    uint32_t wH[2][4][4], wL[2][4][4];
    {
        __nv_bfloat16* Wtmp = (__nv_bfloat16*)shm;   // [128 n][264]
        for (int idx = tid; idx < 128 * 256; idx += 512) {
            int r = idx >> 8, k = idx & 255;
            int g = r >> 5, ui = r & 31;
            float v = p.W[g][(size_t)(u0 + ui) * 768 + 512 + k];
            Wtmp[r * 264 + k] = __float2bfloat16(v);
        }
        __syncthreads();
#pragma unroll
        for (int jn2 = 0; jn2 < 2; jn2++)
#pragma unroll
            for (int kb = 0; kb < 4; kb++) {
                uint32_t a = sb + (uint32_t)((nt * 32 + jn2 * 16 + (lane & 15)) * 528
                                             + kg * 128 + kb * 32 + ((lane >> 4) << 4));
                ldsm_x4(wH[jn2][kb][0], wH[jn2][kb][1], wH[jn2][kb][2], wH[jn2][kb][3], a);
            }
        __syncthreads();
        for (int idx = tid; idx < 128 * 256; idx += 512) {
            int r = idx >> 8, k = idx & 255;
            int g = r >> 5, ui = r & 31;
            float v = p.W[g][(size_t)(u0 + ui) * 768 + 512 + k];
            __nv_bfloat16 hb = __float2bfloat16(v);
            Wtmp[r * 264 + k] = __float2bfloat16(v - __bfloat162float(hb));
        }
        __syncthreads();
#pragma unroll
        for (int jn2 = 0; jn2 < 2; jn2++)
#pragma unroll
            for (int kb = 0; kb < 4; kb++) {
                uint32_t a = sb + (uint32_t)((nt * 32 + jn2 * 16 + (lane & 15)) * 528
                                             + kg * 128 + kb * 32 + ((lane >> 4) << 4));
                ldsm_x4(wL[jn2][kb][0], wL[jn2][kb][1], wL[jn2][kb][2], wL[jn2][kb][3], a);
            }
        __syncthreads();
    }

    __shared__ unsigned s_gen0;
    if (tid == 0) s_gen0 = g_flags[myflag * 32];
    __syncthreads();
    const unsigned gen0 = s_gen0;

    float c = 0.f;
    const size_t xoff = (size_t)(b0 + b) * 1024 + u0 + u;

    float xpre[4];
    {
        const float* Xn = g_X + xoff;
#pragma unroll
        for (int g = 0; g < 4; g++) xpre[g] = __ldcs(Xn + g * 256);
    }

    for (int t = 0; t < 512; t++) {
        // fill h smem (bf16 hi/lo) via cp.async.cg (fresh L2 data, no L1)
        if (t > 0) {
            const __nv_bfloat16* srcH = g_hH[(t + 1) & 1];
            const __nv_bfloat16* srcL = g_hL[(t + 1) & 1];
            int row = tid >> 5, c8 = tid & 31;
            size_t goff = (size_t)(b0 + row) * 256 + c8 * 8;
            uint32_t soff = (uint32_t)(row * 528 + c8 * 16);
            cpa16(sb + soff, srcH + goff);
            cpa16(sb + 8448u + soff, srcL + goff);
            CP_COMMIT();
        }
        // prefetch X(t+1)
        float xnext[4];
        if (t < 511) {
            const float* Xn = g_X + ((size_t)(t + 1) << 18) + xoff;
#pragma unroll
            for (int g = 0; g < 4; g++) xnext[g] = __ldcs(Xn + g * 256);
        }

        if (t > 0) {
            CP_WAIT(0);
            __syncthreads();
            float d[4][4];
#pragma unroll
            for (int j = 0; j < 4; j++)
#pragma unroll
                for (int q = 0; q < 4; q++) d[j][q] = 0.f;

#pragma unroll
            for (int kb = 0; kb < 4; kb++) {
                uint32_t aH[4], aL[4];
                uint32_t ar = sb + (uint32_t)((lane & 15) * 528
                                              + kg * 128 + kb * 32 + ((lane >> 4) << 4));
                ldsm_x4(aH[0], aH[1], aH[2], aH[3], ar);
                ldsm_x4(aL[0], aL[1], aL[2], aL[3], ar + 8448u);
#pragma unroll
                for (int j = 0; j < 4; j++) {
                    mma16816(d[j], aH, wH[j >> 1][kb][j & 1], wH[j >> 1][kb][2 + (j & 1)]);
                    mma16816(d[j], aL, wH[j >> 1][kb][j & 1], wH[j >> 1][kb][2 + (j & 1)]);
                    mma16816(d[j], aH, wL[j >> 1][kb][j & 1], wL[j >> 1][kb][2 + (j & 1)]);
                }
            }
            // scatter partials (rotate-by-8 col swizzle, 128 cols)
#pragma unroll
            for (int j = 0; j < 4; j++) {
                int bl = lane >> 2;
                int n = nt * 32 + j * 8 + (lane & 3) * 2;
                int c0 = (n + 8 * bl) & 127;
                *(float2*)(PS + kg * 2048 + bl * 128 + c0) = make_float2(d[j][0], d[j][1]);
                int bl2 = bl + 8;
                int c2 = (n + 8 * bl2) & 127;
                *(float2*)(PS + kg * 2048 + bl2 * 128 + c2) = make_float2(d[j][2], d[j][3]);
            }
            __syncthreads();
        }

        // reduce + gates
        float S[4];
#pragma unroll
        for (int g = 0; g < 4; g++) S[g] = xpre[g];
        if (t > 0) {
#pragma unroll
            for (int g = 0; g < 4; g++) {
                int cc = (g * 32 + u + 8 * b) & 127;
#pragma unroll
                for (int k2 = 0; k2 < 4; k2++)
                    S[g] += PS[k2 * 2048 + b * 128 + cc];
            }
        }
        float pf = sigm_fast(S[0]);
        float pi = sigm_fast(S[1]);
        float pu = sigm_fast(S[2]);
        float po = sigm_fast(S[3]);
        c = pf * c + pi * pu;
        float h = po * tanh_fast(c);

        __nv_bfloat16 hh = __float2bfloat16(h);
        __nv_bfloat16 hl = __float2bfloat16(h - __bfloat162float(hh));
        size_t hidx = (size_t)(b0 + b) * 256 + u0 + u;
        g_hH[t & 1][hidx] = hh;
        g_hL[t & 1][hidx] = hl;

#pragma unroll
        for (int g = 0; g < 4; g++) xpre[g] = xnext[g];

        if (t < 511) {
            __syncthreads();                  // all h stores issued CTA-wide
            if (tid == 0)
                st_release(&g_flags[myflag * 32], gen0 + (unsigned)t + 1u);
            out[(size_t)t * 65536 + (b0 + b) * 256 + u0 + u] = h;  // overlaps poll
            if (tid < 8) {
                const unsigned* fp = &g_flags[(by * 8 + tid) * 32];
                unsigned want = gen0 + (unsigned)t + 1u;
                while ((int)(ld_acquire(fp) - want) < 0) { }
            }
            __syncthreads();
        } else {
            int gb = b0 + b;
            out[(size_t)t * 65536 + gb * 256 + u0 + u] = h;
            if (out_elems >= 33685504) {
                out[33554432 + gb * 256 + u0 + u] = h;   // hx
                out[33619968 + gb * 256 + u0 + u] = c;   // cx
            }
        }
    }
}

// ---------------------------------------------------------------------------
extern "C" void kernel_launch(void* const* d_in, const int* in_sizes, int n_in,
                              void* d_out, int out_size) {
    const float* x = (const float*)d_in[0];
    P12 p;
    if (n_in >= 13 && in_sizes[3] == 196608) {
        for (int g = 0; g < 4; g++) {
            p.W[g] = (const float*)d_in[1 + 2 * g];
            p.B[g] = (const float*)d_in[2 + 2 * g];
            p.R[g] = (const float*)d_in[9 + g];
        }
    } else {
        for (int g = 0; g < 4; g++) {
            p.W[g] = (const float*)d_in[1 + 3 * g];
            p.B[g] = (const float*)d_in[2 + 3 * g];
            p.R[g] = (const float*)d_in[3 + 3 * g];
        }
    }

    cvt_kernel<<<6144, 256>>>(x, p);

    cudaFuncSetAttribute(g1mma_kernel, cudaFuncAttributeMaxDynamicSharedMemorySize, 98304);
    g1mma_kernel<<<dim3(8, 1024), 256, 98304>>>(p);

    cudaFuncSetAttribute(rnn_mma_kernel, cudaFuncAttributeMaxDynamicSharedMemorySize, 67584);
    rnn_mma_kernel<<<dim3(8, 16), 512, 67584>>>(p, (float*)d_out, out_size);
}

// round 17
// speedup vs baseline: 1.0121x; 1.0121x over previous
#include <cuda_runtime.h>
#include <cuda_bf16.h>
#include <cstdint>

struct P12 { const float* W[4]; const float* B[4]; const float* R[4]; };

// ---------------- persistent device scratch (no allocations allowed) --------
__device__ float g_X[(size_t)512 * 256 * 1024];   // pre-activations [t][b][g*256+u]
__device__ __nv_bfloat16 g_hH[2][256 * 256];      // h hi, ping-pong
__device__ __nv_bfloat16 g_hL[2][256 * 256];      // h lo
__device__ unsigned g_flags[128 * 32];            // per-CTA barrier flags (128B apart)
__device__ __nv_bfloat16 g_Ahi[(size_t)131072 * 512];
__device__ __nv_bfloat16 g_Alo[(size_t)131072 * 512];
__device__ __nv_bfloat16 g_Whi[1024 * 512];       // W (input cols) hi
__device__ __nv_bfloat16 g_Wlo[1024 * 512];

// ---------------- helpers ----------------------------------------------------
__device__ __forceinline__ float ex2a(float x) {
    float r; asm("ex2.approx.f32 %0, %1;" : "=f"(r) : "f"(x)); return r;
}
__device__ __forceinline__ float rcpa(float x) {
    float r; asm("rcp.approx.f32 %0, %1;" : "=f"(r) : "f"(x)); return r;
}
__device__ __forceinline__ float sigm_fast(float x) {
    return rcpa(1.0f + ex2a(-1.4426950408889634f * x));
}
__device__ __forceinline__ float tanh_fast(float x) {
    return 1.0f - 2.0f * rcpa(1.0f + ex2a(2.8853900817779268f * x));
}
__device__ __forceinline__ uint32_t smem_u32(const void* p) {
    uint32_t a; asm("{ .reg .u64 t; cvta.to.shared.u64 t, %1; cvt.u32.u64 %0, t; }"
                    : "=r"(a) : "l"(p)); return a;
}
__device__ __forceinline__ void st_release(unsigned* p, unsigned v) {
    asm volatile("st.release.gpu.u32 [%0], %1;" :: "l"(p), "r"(v) : "memory");
}
__device__ __forceinline__ unsigned ld_acquire(const unsigned* p) {
    unsigned v; asm volatile("ld.acquire.gpu.u32 %0, [%1];" : "=r"(v) : "l"(p) : "memory");
    return v;
}
__device__ __forceinline__ void cpa16(uint32_t smem, const void* g) {
    asm volatile("cp.async.cg.shared.global [%0], [%1], 16;" :: "r"(smem), "l"(g));
}
#define CP_COMMIT() asm volatile("cp.async.commit_group;" ::: "memory")
#define CP_WAIT(n)  asm volatile("cp.async.wait_group %0;" :: "n"(n) : "memory")
#define SWZ(x) ((x) ^ (((x) >> 3) & 0x70))

__device__ __forceinline__ void ldsm_x4(uint32_t& r0, uint32_t& r1, uint32_t& r2,
                                        uint32_t& r3, uint32_t addr) {
    asm volatile("ldmatrix.sync.aligned.m8n8.x4.shared.b16 {%0,%1,%2,%3}, [%4];"
                 : "=r"(r0), "=r"(r1), "=r"(r2), "=r"(r3) : "r"(addr));
}
__device__ __forceinline__ void mma16816(float* d, const uint32_t* a,
                                         uint32_t b0, uint32_t b1) {
    asm volatile("mma.sync.aligned.m16n8k16.row.col.f32.bf16.bf16.f32 "
                 "{%0,%1,%2,%3}, {%4,%5,%6,%7}, {%8,%9}, {%0,%1,%2,%3};"
                 : "+f"(d[0]), "+f"(d[1]), "+f"(d[2]), "+f"(d[3])
                 : "r"(a[0]), "r"(a[1]), "r"(a[2]), "r"(a[3]), "r"(b0), "r"(b1));
}

// ---------------------------------------------------------------------------
// Merged conversion: blocks 0..2047 convert W, blocks 2048..6143 convert x.
// (measured DRAM-bound at ~71% of spec — at its floor)
// ---------------------------------------------------------------------------
__global__ void cvt_kernel(const float* __restrict__ A, P12 p) {
    int bid = blockIdx.x, tid = threadIdx.x;
    if (bid < 2048) {
        int i = bid * 256 + tid;
        if (i >= 1024 * 512) return;
        int nrow = i >> 9, k = i & 511;
        int g = nrow >> 8, u = nrow & 255;
        float v = p.W[g][(size_t)u * 768 + k];
        __nv_bfloat16 h = __float2bfloat16(v);
        g_Whi[i] = h;
        g_Wlo[i] = __float2bfloat16(v - __bfloat162float(h));
    } else {
        size_t i = (size_t)(bid - 2048) * 256 + tid;
        size_t n = (size_t)131072 * 512;
        for (; i < n; i += (size_t)4096 * 256) {
            float v = A[i];
            __nv_bfloat16 h = __float2bfloat16(v);
            g_Ahi[i] = h;
            g_Alo[i] = __float2bfloat16(v - __bfloat162float(h));
        }
    }
}

// ---------------------------------------------------------------------------
// Kernel 1: X[m][n] = x[m].W[n] + (b+r)[n]   — EXACT R15 (3200us winner)
//   CTA 128m x 128n, grid (8,1024). 3-stage cp.async (32KB/stage, 96KB),
//   2 CTAs/SM, 64x32 warp tiles. 24 chunks, PASS-MAJOR order (sp = c>>3).
// ---------------------------------------------------------------------------
__global__ void __launch_bounds__(256, 2) g1mma_kernel(P12 p) {
    extern __shared__ __align__(1024) char sh[];
    uint32_t sb = smem_u32(sh);
    const int tid = threadIdx.x, wid = tid >> 5, lane = tid & 31;
    const int bx = blockIdx.x, n0 = bx * 128;
    const int gate = bx >> 1, ub = (bx & 1) * 128;
    const int m0 = blockIdx.y * 128;
    const int mw = (wid >> 2) * 64, nw = (wid & 3) * 32;

    const __nv_bfloat16* Asrc[3] = { g_Ahi, g_Alo, g_Ahi };
    const __nv_bfloat16* Bsrc[3] = { g_Whi, g_Whi, g_Wlo };

    float d[4][4][4];
#pragma unroll
    for (int i = 0; i < 4; i++)
#pragma unroll
        for (int j = 0; j < 4; j++)
#pragma unroll
            for (int q = 0; q < 4; q++) d[i][j][q] = 0.f;

    const int frow = tid >> 1, fsl = (tid & 1) * 4;  // 2 threads/row, 4 slots each

    auto stage_fill = [&](int c, int s) {
        int sp = c >> 3, kc = (c & 7) << 6;          // pass-major (R15)
        const __nv_bfloat16* Ap = Asrc[sp] + (size_t)(m0 + frow) * 512 + kc;
        const __nv_bfloat16* Bp = Bsrc[sp] + (size_t)(n0 + frow) * 512 + kc;
        uint32_t ab = sb + s * 32768;
        uint32_t bb = ab + 16384;
#pragma unroll
        for (int j = 0; j < 4; j++) {
            cpa16(ab + SWZ((uint32_t)(frow * 128 + (fsl + j) * 16)), Ap + (fsl + j) * 8);
            cpa16(bb + SWZ((uint32_t)(frow * 128 + (fsl + j) * 16)), Bp + (fsl + j) * 8);
        }
    };

    stage_fill(0, 0); CP_COMMIT();
    stage_fill(1, 1); CP_COMMIT();

    int cs = 0, fs = 2;                      // compute stage, fill stage
    for (int c = 0; c < 24; c++) {
        CP_WAIT(1);                           // group c drained
        __syncthreads();
        if (c + 2 < 24) { stage_fill(c + 2, fs); }
        CP_COMMIT();

        const uint32_t sA = sb + cs * 32768, sB = sA + 16384;
#pragma unroll
        for (int k16 = 0; k16 < 4; k16++) {
            const uint32_t colb = k16 * 32 + ((lane >> 4) << 4);
            uint32_t a[4][4], b[2][4];
#pragma unroll
            for (int im = 0; im < 4; im++) {
                int r = mw + im * 16 + (lane & 15);
                ldsm_x4(a[im][0], a[im][1], a[im][2], a[im][3],
                        sA + SWZ((uint32_t)(r * 128 + colb)));
            }
#pragma unroll
            for (int jn = 0; jn < 2; jn++) {
                int r = nw + jn * 16 + (lane & 15);
                ldsm_x4(b[jn][0], b[jn][1], b[jn][2], b[jn][3],
                        sB + SWZ((uint32_t)(r * 128 + colb)));
            }
#pragma unroll
            for (int im = 0; im < 4; im++)
#pragma unroll
                for (int j = 0; j < 4; j++)
                    mma16816(d[im][j], a[im], b[j >> 1][j & 1], b[j >> 1][2 + (j & 1)]);
        }
        cs = (cs == 2) ? 0 : cs + 1;
        fs = (fs == 2) ? 0 : fs + 1;
    }

    // epilogue: registers -> g_X with bias+rot
#pragma unroll
    for (int j = 0; j < 4; j++) {
        int nl = nw + j * 8 + (lane & 3) * 2;
        int u = ub + nl;
        float bv0 = p.B[gate][u] + p.R[gate][u];
        float bv1 = p.B[gate][u + 1] + p.R[gate][u + 1];
#pragma unroll
        for (int im = 0; im < 4; im++) {
            int m = m0 + mw + im * 16 + (lane >> 2);
            float2 v0 = { d[im][j][0] + bv0, d[im][j][1] + bv1 };
            float2 v1 = { d[im][j][2] + bv0, d[im][j][3] + bv1 };
            *(float2*)(g_X + (size_t)m * 1024 + n0 + nl) = v0;
            *(float2*)(g_X + (size_t)(m + 8) * 1024 + n0 + nl) = v1;
        }
    }
}

// ---------------------------------------------------------------------------
// Kernel 2: persistent recurrence, tensorized — EXACT R15 (3200us winner).
// Grid (8 unit-tiles, 16 batch-groups), 512 threads = 16 warps.
// Wh frags (bf16 hi/lo) in registers; h exchanged via L2 (__ldcg + STS);
// 8-poller flag barrier per step.
// ---------------------------------------------------------------------------
__global__ void __launch_bounds__(512, 1) rnn_mma_kernel(P12 p, float* __restrict__ out,
                                                         int out_elems) {
    extern __shared__ __align__(16) char shm[];
    float* PS = (float*)(shm + 16896);
    const uint32_t sb = smem_u32(shm);

    const int tid = threadIdx.x, w = tid >> 5, lane = tid & 31;
    const int kg = w & 3, nt = w >> 2;               // kg 0..3, nt 0..3
    const int b = tid >> 5, u = tid & 31;            // gate-phase: batch=warp, unit=lane
    const int u0 = blockIdx.x * 32, by = blockIdx.y, b0 = by * 16;
    const int myflag = by * 8 + blockIdx.x;

    // ---- init: stage Wh (hidden cols) as bf16, ldsm frags to registers
    uint32_t wH[2][4][4], wL[2][4][4];
    {
        __nv_bfloat16* Wtmp = (__nv_bfloat16*)shm;   // [128 n][264]
        for (int idx = tid; idx < 128 * 256; idx += 512) {
            int r = idx >> 8, k = idx & 255;
            int g = r >> 5, ui = r & 31;
            float v = p.W[g][(size_t)(u0 + ui) * 768 + 512 + k];
            Wtmp[r * 264 + k] = __float2bfloat16(v);
        }
        __syncthreads();
#pragma unroll
        for (int jn2 = 0; jn2 < 2; jn2++)
#pragma unroll
            for (int kb = 0; kb < 4; kb++) {
                uint32_t a = sb + (uint32_t)((nt * 32 + jn2 * 16 + (lane & 15)) * 528
                                             + kg * 128 + kb * 32 + ((lane >> 4) << 4));
                ldsm_x4(wH[jn2][kb][0], wH[jn2][kb][1], wH[jn2][kb][2], wH[jn2][kb][3], a);
            }
        __syncthreads();
        for (int idx = tid; idx < 128 * 256; idx += 512) {
            int r = idx >> 8, k = idx & 255;
            int g = r >> 5, ui = r & 31;
            float v = p.W[g][(size_t)(u0 + ui) * 768 + 512 + k];
            __nv_bfloat16 hb = __float2bfloat16(v);
            Wtmp[r * 264 + k] = __float2bfloat16(v - __bfloat162float(hb));
        }
        __syncthreads();
#pragma unroll
        for (int jn2 = 0; jn2 < 2; jn2++)
#pragma unroll
            for (int kb = 0; kb < 4; kb++) {
                uint32_t a = sb + (uint32_t)((nt * 32 + jn2 * 16 + (lane & 15)) * 528
                                             + kg * 128 + kb * 32 + ((lane >> 4) << 4));
                ldsm_x4(wL[jn2][kb][0], wL[jn2][kb][1], wL[jn2][kb][2], wL[jn2][kb][3], a);
            }
        __syncthreads();
    }

    __shared__ unsigned s_gen0;
    if (tid == 0) s_gen0 = g_flags[myflag * 32];
    __syncthreads();
    const unsigned gen0 = s_gen0;

    float c = 0.f;
    const size_t xoff = (size_t)(b0 + b) * 1024 + u0 + u;

    float xpre[4];
    {
        const float* Xn = g_X + xoff;
#pragma unroll
        for (int g = 0; g < 4; g++) xpre[g] = __ldcs(Xn + g * 256);
    }

    for (int t = 0; t < 512; t++) {
        // fill h smem (bf16 hi/lo): 16 batches x 256 units, 1 uint4 per array
        if (t > 0) {
            const uint4* srcH = (const uint4*)(g_hH[(t + 1) & 1]);
            const uint4* srcL = (const uint4*)(g_hL[(t + 1) & 1]);
            int row = tid >> 5, c8 = tid & 31;
            uint4 vh = __ldcg(srcH + (size_t)(b0 + row) * 32 + c8);
            uint4 vl = __ldcg(srcL + (size_t)(b0 + row) * 32 + c8);
            *(uint4*)(shm + row * 528 + c8 * 16) = vh;
            *(uint4*)(shm + 8448 + row * 528 + c8 * 16) = vl;
        }
        // prefetch X(t+1)
        float xnext[4];
        if (t < 511) {
            const float* Xn = g_X + ((size_t)(t + 1) << 18) + xoff;
#pragma unroll
            for (int g = 0; g < 4; g++) xnext[g] = __ldcs(Xn + g * 256);
        }

        if (t > 0) {
            __syncthreads();
            float d[4][4];
#pragma unroll
            for (int j = 0; j < 4; j++)
#pragma unroll
                for (int q = 0; q < 4; q++) d[j][q] = 0.f;

#pragma unroll
            for (int kb = 0; kb < 4; kb++) {
                uint32_t aH[4], aL[4];
                uint32_t ar = sb + (uint32_t)((lane & 15) * 528
                                              + kg * 128 + kb * 32 + ((lane >> 4) << 4));
                ldsm_x4(aH[0], aH[1], aH[2], aH[3], ar);
                ldsm_x4(aL[0], aL[1], aL[2], aL[3], ar + 8448u);
#pragma unroll
                for (int j = 0; j < 4; j++) {
                    mma16816(d[j], aH, wH[j >> 1][kb][j & 1], wH[j >> 1][kb][2 + (j & 1)]);
                    mma16816(d[j], aL, wH[j >> 1][kb][j & 1], wH[j >> 1][kb][2 + (j & 1)]);
                    mma16816(d[j], aH, wL[j >> 1][kb][j & 1], wL[j >> 1][kb][2 + (j & 1)]);
                }
            }
            // scatter partials (rotate-by-8 col swizzle, 128 cols)
#pragma unroll
            for (int j = 0; j < 4; j++) {
                int bl = lane >> 2;
                int n = nt * 32 + j * 8 + (lane & 3) * 2;
                int c0 = (n + 8 * bl) & 127;
                *(float2*)(PS + kg * 2048 + bl * 128 + c0) = make_float2(d[j][0], d[j][1]);
                int bl2 = bl + 8;
                int c2 = (n + 8 * bl2) & 127;
                *(float2*)(PS + kg * 2048 + bl2 * 128 + c2) = make_float2(d[j][2], d[j][3]);
            }
            __syncthreads();
        }

        // reduce + gates
        float S[4];
#pragma unroll
        for (int g = 0; g < 4; g++) S[g] = xpre[g];
        if (t > 0) {
#pragma unroll
            for (int g = 0; g < 4; g++) {
                int cc = (g * 32 + u + 8 * b) & 127;
#pragma unroll
                for (int k2 = 0; k2 < 4; k2++)
                    S[g] += PS[k2 * 2048 + b * 128 + cc];
            }
        }
        float pf = sigm_fast(S[0]);
        float pi = sigm_fast(S[1]);
        float pu = sigm_fast(S[2]);
        float po = sigm_fast(S[3]);
        c = pf * c + pi * pu;
        float h = po * tanh_fast(c);

        __nv_bfloat16 hh = __float2bfloat16(h);
        __nv_bfloat16 hl = __float2bfloat16(h - __bfloat162float(hh));
        size_t hidx = (size_t)(b0 + b) * 256 + u0 + u;
        g_hH[t & 1][hidx] = hh;
        g_hL[t & 1][hidx] = hl;

#pragma unroll
        for (int g = 0; g < 4; g++) xpre[g] = xnext[g];

        if (t < 511) {
            __syncthreads();                  // all h stores issued CTA-wide
            if (tid == 0)
                st_release(&g_flags[myflag * 32], gen0 + (unsigned)t + 1u);
            out[(size_t)t * 65536 + (b0 + b) * 256 + u0 + u] = h;  // overlaps poll
            if (tid < 8) {
                const unsigned* fp = &g_flags[(by * 8 + tid) * 32];
                unsigned want = gen0 + (unsigned)t + 1u;
                while ((int)(ld_acquire(fp) - want) < 0) { }
            }
            __syncthreads();
        } else {
            int gb = b0 + b;
            out[(size_t)t * 65536 + gb * 256 + u0 + u] = h;
            if (out_elems >= 33685504) {
                out[33554432 + gb * 256 + u0 + u] = h;   // hx
                out[33619968 + gb * 256 + u0 + u] = c;   // cx
            }
        }
    }
}

// ---------------------------------------------------------------------------
extern "C" void kernel_launch(void* const* d_in, const int* in_sizes, int n_in,
                              void* d_out, int out_size) {
    const float* x = (const float*)d_in[0];
    P12 p;
    if (n_in >= 13 && in_sizes[3] == 196608) {
        for (int g = 0; g < 4; g++) {
            p.W[g] = (const float*)d_in[1 + 2 * g];
            p.B[g] = (const float*)d_in[2 + 2 * g];
            p.R[g] = (const float*)d_in[9 + g];
        }
    } else {
        for (int g = 0; g < 4; g++) {
            p.W[g] = (const float*)d_in[1 + 3 * g];
            p.B[g] = (const float*)d_in[2 + 3 * g];
            p.R[g] = (const float*)d_in[3 + 3 * g];
        }
    }

    cvt_kernel<<<6144, 256>>>(x, p);

    cudaFuncSetAttribute(g1mma_kernel, cudaFuncAttributeMaxDynamicSharedMemorySize, 98304);
    g1mma_kernel<<<dim3(8, 1024), 256, 98304>>>(p);

    cudaFuncSetAttribute(rnn_mma_kernel, cudaFuncAttributeMaxDynamicSharedMemorySize, 67584);
    rnn_mma_kernel<<<dim3(8, 16), 512, 67584>>>(p, (float*)d_out, out_size);
}